// round 2
// baseline (speedup 1.0000x reference)
#include <cuda_runtime.h>
#include <math.h>

// Problem constants (fixed by the dataset)
#define Nn 20000
#define Ee 320000
#define Bb 128
#define Ff 128
#define Hh 256
#define EDd 16
#define Gg 16
#define Pp 2000
#define Ll 4
#define ZD (Hh + Gg)          // 272
#define K1 (2 * Hh + 1 + EDd) // 529

// ---------------- scratch (device globals; no allocation allowed) ----------
__device__ float g_h[Nn * Hh];
__device__ float g_hout[Nn * Hh];
__device__ float g_n1[Nn * Hh];
__device__ float g_agg[Nn * Hh];
__device__ float g_coord[Nn * 3];
__device__ float g_cnt[Nn];
__device__ float g_diff[Ee * 3];
__device__ float g_radial[Ee];
__device__ float g_m1[(size_t)Ee * Hh];
__device__ float g_m2[(size_t)Ee * Hh];
__device__ float g_c[Ee];
__device__ float g_z[Bb * ZD];
__device__ float g_t[Bb * Hh];
__device__ int   g_s[Bb];
__device__ int   g_e[Bb];

// ---------------- generic tiled SGEMM -------------------------------------
// C[M,Ncol] = epi( A'[M,K] @ Bw[K,Ncol] + bias )
// AMODE 0: A plain row-major
// AMODE 1: A(i,k) = k<H ? h[row[i],k] : k<2H ? h[col[i],k-H] : k==2H ? radial[i]
//                   : edge_attr[i, k-2H-1]           (K = 529)
// AMODE 2: A(i,k) = k<H ? h[i,k] : agg[i,k-H]        (K = 512)
// EPI 0: C = v ; EPI 1: C = silu(v) ; EPI 2: C += v
template <int AMODE, int EPI>
__global__ void gemm_k(const float* __restrict__ A, const float* __restrict__ Bw,
                       const float* __restrict__ bias, float* __restrict__ C,
                       int M, int K, int Ncol,
                       const int* __restrict__ rowIdx, const int* __restrict__ colIdx,
                       const float* __restrict__ hbuf, const float* __restrict__ aggbuf,
                       const float* __restrict__ radial, const float* __restrict__ eattr)
{
    __shared__ float As[16][64];
    __shared__ float Bs[16][64];
    const int tid = threadIdx.x;
    const int tx = tid & 15, ty = tid >> 4;
    const int i0 = blockIdx.y * 64, j0 = blockIdx.x * 64;

    const int a_row = tid >> 2;        // 0..63
    const int a_k   = (tid & 3) * 4;   // 0,4,8,12
    const int b_k   = tid >> 4;        // 0..15
    const int b_j   = (tid & 15) * 4;  // 0..60

    float acc[4][4] = {};

    const int gi = i0 + a_row;
    int r = 0, cc = 0;
    if (AMODE == 1 && gi < M) { r = __ldg(&rowIdx[gi]); cc = __ldg(&colIdx[gi]); }

    for (int k0 = 0; k0 < K; k0 += 16) {
#pragma unroll
        for (int q = 0; q < 4; q++) {
            int gk = k0 + a_k + q;
            float v = 0.f;
            if (gi < M && gk < K) {
                if (AMODE == 0) {
                    v = A[(size_t)gi * K + gk];
                } else if (AMODE == 1) {
                    if (gk < Hh)            v = hbuf[r * Hh + gk];
                    else if (gk < 2 * Hh)   v = hbuf[cc * Hh + gk - Hh];
                    else if (gk == 2 * Hh)  v = radial[gi];
                    else                    v = eattr[gi * EDd + gk - (2 * Hh + 1)];
                } else {
                    if (gk < Hh) v = hbuf[gi * Hh + gk];
                    else         v = aggbuf[gi * Hh + gk - Hh];
                }
            }
            As[a_k + q][a_row] = v;
        }
        {
            int gk = k0 + b_k;
#pragma unroll
            for (int q = 0; q < 4; q++) {
                int gj = j0 + b_j + q;
                Bs[b_k][b_j + q] = (gk < K && gj < Ncol) ? Bw[(size_t)gk * Ncol + gj] : 0.f;
            }
        }
        __syncthreads();
#pragma unroll
        for (int kk = 0; kk < 16; kk++) {
            float4 ra = *(const float4*)&As[kk][ty * 4];
            float4 rb = *(const float4*)&Bs[kk][tx * 4];
            float av[4] = {ra.x, ra.y, ra.z, ra.w};
            float bv[4] = {rb.x, rb.y, rb.z, rb.w};
#pragma unroll
            for (int m = 0; m < 4; m++)
#pragma unroll
                for (int n = 0; n < 4; n++)
                    acc[m][n] += av[m] * bv[n];
        }
        __syncthreads();
    }

#pragma unroll
    for (int m = 0; m < 4; m++) {
        int oi = i0 + ty * 4 + m;
        if (oi >= M) continue;
#pragma unroll
        for (int n = 0; n < 4; n++) {
            int oj = j0 + tx * 4 + n;
            if (oj >= Ncol) continue;
            float v = acc[m][n] + bias[oj];
            if (EPI == 1) v = v / (1.f + expf(-v));
            if (EPI == 2) C[(size_t)oi * Ncol + oj] += v;
            else          C[(size_t)oi * Ncol + oj] = v;
        }
    }
}

// ---------------- small helper kernels -------------------------------------
__global__ void init_kernel(const float* __restrict__ pos, float* __restrict__ coord,
                            float* __restrict__ cnt)
{
    int i = blockIdx.x * blockDim.x + threadIdx.x;
    if (i >= Nn) return;
    cnt[i] = 0.f;
    coord[3 * i + 0] = pos[3 * i + 0];
    coord[3 * i + 1] = pos[3 * i + 1];
    coord[3 * i + 2] = pos[3 * i + 2];
}

__global__ void count_kernel(const int* __restrict__ row, float* __restrict__ cnt)
{
    int e = blockIdx.x * blockDim.x + threadIdx.x;
    if (e >= Ee) return;
    atomicAdd(&cnt[row[e]], 1.f);
}

__global__ void edge_geom_kernel(const float* __restrict__ coord,
                                 const int* __restrict__ row, const int* __restrict__ col,
                                 float* __restrict__ diff, float* __restrict__ radial)
{
    int e = blockIdx.x * blockDim.x + threadIdx.x;
    if (e >= Ee) return;
    int r = row[e], c = col[e];
    float dx = coord[3 * r + 0] - coord[3 * c + 0];
    float dy = coord[3 * r + 1] - coord[3 * c + 1];
    float dz = coord[3 * r + 2] - coord[3 * c + 2];
    diff[3 * e + 0] = dx; diff[3 * e + 1] = dy; diff[3 * e + 2] = dz;
    radial[e] = dx * dx + dy * dy + dz * dz;
}

__global__ void coord_c_kernel(const float* __restrict__ t, const float* __restrict__ wc2,
                               float* __restrict__ c)
{
    int warp = (blockIdx.x * blockDim.x + threadIdx.x) >> 5;
    int lane = threadIdx.x & 31;
    if (warp >= Ee) return;
    float s = 0.f;
#pragma unroll
    for (int j = lane; j < Hh; j += 32) s += t[(size_t)warp * Hh + j] * wc2[j];
#pragma unroll
    for (int o = 16; o; o >>= 1) s += __shfl_down_sync(0xffffffffu, s, o);
    if (lane == 0) c[warp] = s;
}

__global__ void zero_kernel(float* __restrict__ p, int n)
{
    int i = blockIdx.x * blockDim.x + threadIdx.x;
    if (i < n) p[i] = 0.f;
}

// agg[row[e]] += m2[e,:]; coord[row[e]] += diff[e]*c[e]/max(cnt,1)
__global__ void scatter_kernel(const float* __restrict__ m2, const float* __restrict__ diff,
                               const float* __restrict__ c, const int* __restrict__ row,
                               const float* __restrict__ cnt, float* __restrict__ agg,
                               float* __restrict__ coord)
{
    int e = blockIdx.x;
    int j = threadIdx.x;  // 256 threads
    int r = row[e];
    atomicAdd(&agg[r * Hh + j], m2[(size_t)e * Hh + j]);
    if (j < 3) {
        float inv = 1.f / fmaxf(cnt[r], 1.f);
        atomicAdd(&coord[r * 3 + j], diff[e * 3 + j] * c[e] * inv);
    }
}

__global__ void bounds_kernel(const int* __restrict__ batch, int* __restrict__ s,
                              int* __restrict__ e)
{
    int i = blockIdx.x * blockDim.x + threadIdx.x;
    if (i >= Nn) return;
    int b = batch[i];
    if (i == 0) s[b] = 0;
    else {
        int pb = batch[i - 1];
        if (pb != b) { s[b] = i; e[pb] = i; }
    }
    if (i == Nn - 1) e[b] = Nn;
}

__global__ void pool_kernel(const float* __restrict__ hout, const int* __restrict__ s,
                            const int* __restrict__ e, const float* __restrict__ frag,
                            const float* __restrict__ addf, float* __restrict__ z)
{
    int b = blockIdx.x;
    int j = threadIdx.x;  // 256
    float m = -INFINITY;
    int n0 = s[b], n1 = e[b];
    for (int n = n0; n < n1; n++) m = fmaxf(m, hout[(size_t)n * Hh + j]);
    z[b * ZD + j] = m;
    if (j < 8)       z[b * ZD + Hh + j] = frag[b * 8 + j];
    else if (j < 16) z[b * ZD + Hh + j] = addf[b * 8 + (j - 8)];
}

// ---------------- launch ----------------------------------------------------
extern "C" void kernel_launch(void* const* d_in, const int* in_sizes, int n_in,
                              void* d_out, int out_size)
{
    const float* x        = (const float*)d_in[0];
    const float* pos      = (const float*)d_in[1];
    const float* eattr    = (const float*)d_in[2];
    const float* frag     = (const float*)d_in[3];
    const float* addf     = (const float*)d_in[4];
    const int*   eidx     = (const int*)d_in[5];
    const int*   batch    = (const int*)d_in[6];
    const float* emb_in_w = (const float*)d_in[7];
    const float* emb_in_b = (const float*)d_in[8];
    const float* edge_w1  = (const float*)d_in[9];
    const float* edge_b1  = (const float*)d_in[10];
    const float* edge_w2  = (const float*)d_in[11];
    const float* edge_b2  = (const float*)d_in[12];
    const float* node_w1  = (const float*)d_in[13];
    const float* node_b1  = (const float*)d_in[14];
    const float* node_w2  = (const float*)d_in[15];
    const float* node_b2  = (const float*)d_in[16];
    const float* coord_w1 = (const float*)d_in[17];
    const float* coord_b1 = (const float*)d_in[18];
    const float* coord_w2 = (const float*)d_in[19];
    const float* emb_out_w= (const float*)d_in[20];
    const float* emb_out_b= (const float*)d_in[21];
    const float* res_w1   = (const float*)d_in[22];
    const float* res_b1   = (const float*)d_in[23];
    const float* res_w2   = (const float*)d_in[24];
    const float* res_b2   = (const float*)d_in[25];
    const float* head_w   = (const float*)d_in[26];
    const float* head_b   = (const float*)d_in[27];
    float* out = (float*)d_out;
    const int* row = eidx;
    const int* col = eidx + Ee;

    float *h, *hout, *n1, *agg, *coord, *cnt, *diff, *radial, *m1, *m2, *cbuf, *z, *tbuf;
    int *sb, *eb;
    cudaGetSymbolAddress((void**)&h, g_h);
    cudaGetSymbolAddress((void**)&hout, g_hout);
    cudaGetSymbolAddress((void**)&n1, g_n1);
    cudaGetSymbolAddress((void**)&agg, g_agg);
    cudaGetSymbolAddress((void**)&coord, g_coord);
    cudaGetSymbolAddress((void**)&cnt, g_cnt);
    cudaGetSymbolAddress((void**)&diff, g_diff);
    cudaGetSymbolAddress((void**)&radial, g_radial);
    cudaGetSymbolAddress((void**)&m1, g_m1);
    cudaGetSymbolAddress((void**)&m2, g_m2);
    cudaGetSymbolAddress((void**)&cbuf, g_c);
    cudaGetSymbolAddress((void**)&z, g_z);
    cudaGetSymbolAddress((void**)&tbuf, g_t);
    cudaGetSymbolAddress((void**)&sb, g_s);
    cudaGetSymbolAddress((void**)&eb, g_e);

    const dim3 T(256);
    const dim3 gEdge(Hh / 64, Ee / 64);           // 4 x 5000
    const dim3 gNode(Hh / 64, (Nn + 63) / 64);    // 4 x 313

    init_kernel<<<(Nn + 255) / 256, T>>>(pos, coord, cnt);
    count_kernel<<<(Ee + 255) / 256, T>>>(row, cnt);

    // h = x @ emb_in_w + b
    gemm_k<0, 0><<<gNode, T>>>(x, emb_in_w, emb_in_b, h, Nn, Ff, Hh,
                               nullptr, nullptr, nullptr, nullptr, nullptr, nullptr);

    for (int l = 0; l < Ll; l++) {
        edge_geom_kernel<<<(Ee + 255) / 256, T>>>(coord, row, col, diff, radial);
        // m1 = silu(concat(h[row],h[col],radial,ea) @ W1 + b1)
        gemm_k<1, 1><<<gEdge, T>>>(nullptr, edge_w1 + (size_t)l * K1 * Hh, edge_b1 + l * Hh,
                                   m1, Ee, K1, Hh, row, col, h, nullptr, radial, eattr);
        // m2 = silu(m1 @ W2 + b2)
        gemm_k<0, 1><<<gEdge, T>>>(m1, edge_w2 + (size_t)l * Hh * Hh, edge_b2 + l * Hh,
                                   m2, Ee, Hh, Hh, nullptr, nullptr, nullptr, nullptr, nullptr, nullptr);
        // t (in m1) = silu(m2 @ Wc1 + bc1)
        gemm_k<0, 1><<<gEdge, T>>>(m2, coord_w1 + (size_t)l * Hh * Hh, coord_b1 + l * Hh,
                                   m1, Ee, Hh, Hh, nullptr, nullptr, nullptr, nullptr, nullptr, nullptr);
        // c = t @ Wc2
        coord_c_kernel<<<(Ee * 32 + 255) / 256, T>>>(m1, coord_w2 + l * Hh, cbuf);
        zero_kernel<<<(Nn * Hh + 255) / 256, T>>>(agg, Nn * Hh);
        scatter_kernel<<<Ee, T>>>(m2, diff, cbuf, row, cnt, agg, coord);
        // n1 = silu(concat(h,agg) @ nW1 + nb1)
        gemm_k<2, 1><<<gNode, T>>>(nullptr, node_w1 + (size_t)l * 2 * Hh * Hh, node_b1 + l * Hh,
                                   n1, Nn, 2 * Hh, Hh, nullptr, nullptr, h, agg, nullptr, nullptr);
        // h += n1 @ nW2 + nb2
        gemm_k<0, 2><<<gNode, T>>>(n1, node_w2 + (size_t)l * Hh * Hh, node_b2 + l * Hh,
                                   h, Nn, Hh, Hh, nullptr, nullptr, nullptr, nullptr, nullptr, nullptr);
    }

    // hout = h @ emb_out_w + b
    gemm_k<0, 0><<<gNode, T>>>(h, emb_out_w, emb_out_b, hout, Nn, Hh, Hh,
                               nullptr, nullptr, nullptr, nullptr, nullptr, nullptr);

    bounds_kernel<<<(Nn + 255) / 256, T>>>(batch, sb, eb);
    pool_kernel<<<Bb, T>>>(hout, sb, eb, frag, addf, z);

    // t = silu(z @ res_w1 + b)
    gemm_k<0, 1><<<dim3(4, 2), T>>>(z, res_w1, res_b1, tbuf, Bb, ZD, Hh,
                                    nullptr, nullptr, nullptr, nullptr, nullptr, nullptr);
    // z += t @ res_w2 + b
    gemm_k<0, 2><<<dim3((ZD + 63) / 64, 2), T>>>(tbuf, res_w2, res_b2, z, Bb, Hh, ZD,
                                    nullptr, nullptr, nullptr, nullptr, nullptr, nullptr);
    // out = z @ head_w + head_b
    gemm_k<0, 0><<<dim3((Pp + 63) / 64, 2), T>>>(z, head_w, head_b, out, Bb, ZD, Pp,
                                    nullptr, nullptr, nullptr, nullptr, nullptr, nullptr);
}

// round 3
// speedup vs baseline: 3.0098x; 3.0098x over previous
#include <cuda_runtime.h>
#include <math.h>
#include <stdint.h>

// Problem constants (fixed by the dataset)
#define Nn 20000
#define Ee 320000
#define Bb 128
#define Ff 128
#define Hh 256
#define EDd 16
#define Gg 16
#define Pp 2000
#define Ll 4
#define ZD (Hh + Gg)          // 272
#define K1 (2 * Hh + 1 + EDd) // 529

// ---------------- scratch (device globals; no allocation allowed) ----------
__device__ float g_h[Nn * Hh];
__device__ float g_hout[Nn * Hh];
__device__ float g_n1[Nn * Hh];
__device__ float g_agg[Nn * Hh];
__device__ float g_coord[Nn * 3];
__device__ float g_cnt[Nn];
__device__ float g_diff[Ee * 3];
__device__ float g_radial[Ee];
__device__ float g_m1[(size_t)Ee * Hh];
__device__ float g_m2[(size_t)Ee * Hh];
__device__ float g_c[Ee];
__device__ float g_z[Bb * ZD];
__device__ float g_t[Bb * Hh];
__device__ int   g_s[Bb];
__device__ int   g_e[Bb];

__device__ __forceinline__ uint32_t f2tf32(float x) {
    uint32_t r;
    asm("cvt.rna.tf32.f32 %0, %1;" : "=r"(r) : "f"(x));
    return r;
}

__device__ __forceinline__ void mma_tf32(float* d, const uint32_t* a, const uint32_t* b) {
    asm volatile(
        "mma.sync.aligned.m16n8k8.row.col.f32.tf32.tf32.f32 "
        "{%0,%1,%2,%3}, {%4,%5,%6,%7}, {%8,%9}, {%0,%1,%2,%3};"
        : "+f"(d[0]), "+f"(d[1]), "+f"(d[2]), "+f"(d[3])
        : "r"(a[0]), "r"(a[1]), "r"(a[2]), "r"(a[3]), "r"(b[0]), "r"(b[1]));
}

__device__ __forceinline__ float silu_f(float v) { return v / (1.f + expf(-v)); }

// ---------------- tf32 tensor-core GEMM ------------------------------------
// C[M,Ncol] = epi( A'[M,K] @ Bw[K,Ncol] + bias )
// AMODE 0: A plain row-major
// AMODE 1: A(i,k) = k<H ? h[row[i],k] : k<2H ? h[col[i],k-H] : k==2H ? radial[i]
//                   : edge_attr[i,k-2H-1]  (K=529)
// AMODE 2: A(i,k) = k<H ? h[i,k] : agg[i,k-H]  (K=512)
// EPI 0: C=v ; 1: C=silu(v) ; 2: C+=v
// EPI 3: no C write; cbuf[i] += sum_j silu(v_ij)*wc2[j]   (atomic)
// EPI 4: C=silu(v) AND agg[row[i]] += silu(v)             (atomic)
// Block 128x128x32, 128 threads (4 warps of 64x64).
template <int AMODE, int EPI>
__global__ __launch_bounds__(128, 2)
void gemm_tc(const float* __restrict__ A, const float* __restrict__ Bw,
             const float* __restrict__ bias, float* __restrict__ C,
             int M, int K, int Ncol,
             const int* __restrict__ rowIdx, const int* __restrict__ colIdx,
             const float* __restrict__ hbuf, const float* __restrict__ aggbuf,
             const float* __restrict__ radial, const float* __restrict__ eattr,
             const float* __restrict__ wc2, float* __restrict__ cbuf,
             float* __restrict__ aggout)
{
    __shared__ uint32_t As[32][136];  // [k][m], padded
    __shared__ uint32_t Bs[32][136];  // [k][n], padded

    const int tid  = threadIdx.x;
    const int lane = tid & 31;
    const int wid  = tid >> 5;
    const int wm   = (wid >> 1) * 64;   // warp row base in tile
    const int wn   = (wid & 1) * 64;    // warp col base in tile
    const int g    = lane >> 2;
    const int c    = lane & 3;

    const int i0 = blockIdx.y * 128;
    const int j0 = blockIdx.x * 128;

    const int gi = i0 + tid;            // A-load: one row per thread
    const bool rowok = gi < M;
    int r = 0, cc = 0;
    if (AMODE == 1 && rowok) { r = __ldg(&rowIdx[gi]); cc = __ldg(&colIdx[gi]); }

    float acc[4][8][4];
#pragma unroll
    for (int a = 0; a < 4; a++)
#pragma unroll
        for (int b = 0; b < 8; b++)
#pragma unroll
            for (int q = 0; q < 4; q++) acc[a][b][q] = 0.f;

    for (int k0 = 0; k0 < K; k0 += 32) {
        // ---- load A slice [128 rows x 32 k] ----
        if (AMODE == 1 && k0 >= 512) {
#pragma unroll
            for (int j = 0; j < 32; j++) {
                int gk = k0 + j;
                float v = 0.f;
                if (rowok && gk < K) {
                    if (gk == 2 * Hh) v = radial[gi];
                    else              v = eattr[gi * EDd + gk - (2 * Hh + 1)];
                }
                As[j][tid] = f2tf32(v);
            }
        } else {
            const float* base;
            if (AMODE == 0)      base = A + (size_t)gi * K + k0;
            else if (AMODE == 1) base = (k0 < Hh) ? hbuf + (size_t)r * Hh + k0
                                                  : hbuf + (size_t)cc * Hh + (k0 - Hh);
            else                 base = (k0 < Hh) ? hbuf + (size_t)gi * Hh + k0
                                                  : aggbuf + (size_t)gi * Hh + (k0 - Hh);
#pragma unroll
            for (int j4 = 0; j4 < 8; j4++) {
                float4 v = make_float4(0.f, 0.f, 0.f, 0.f);
                if (rowok) v = *(const float4*)(base + j4 * 4);
                As[j4 * 4 + 0][tid] = f2tf32(v.x);
                As[j4 * 4 + 1][tid] = f2tf32(v.y);
                As[j4 * 4 + 2][tid] = f2tf32(v.z);
                As[j4 * 4 + 3][tid] = f2tf32(v.w);
            }
        }
        // ---- load B slice [32 k x 128 n] ----
#pragma unroll
        for (int it = 0; it < 8; it++) {
            int lin = (it * 128 + tid) * 4;
            int k = lin >> 7, n = lin & 127;
            int gk = k0 + k;
            float4 v = make_float4(0.f, 0.f, 0.f, 0.f);
            if (gk < K) v = *(const float4*)&Bw[(size_t)gk * Ncol + j0 + n];
            Bs[k][n + 0] = f2tf32(v.x);
            Bs[k][n + 1] = f2tf32(v.y);
            Bs[k][n + 2] = f2tf32(v.z);
            Bs[k][n + 3] = f2tf32(v.w);
        }
        __syncthreads();

#pragma unroll
        for (int ks = 0; ks < 4; ks++) {
            uint32_t af[4][4];
#pragma unroll
            for (int mf = 0; mf < 4; mf++) {
                int m = wm + mf * 16 + g;
                af[mf][0] = As[ks * 8 + c][m];
                af[mf][1] = As[ks * 8 + c][m + 8];
                af[mf][2] = As[ks * 8 + c + 4][m];
                af[mf][3] = As[ks * 8 + c + 4][m + 8];
            }
            uint32_t bf[8][2];
#pragma unroll
            for (int nf = 0; nf < 8; nf++) {
                int n = wn + nf * 8 + g;
                bf[nf][0] = Bs[ks * 8 + c][n];
                bf[nf][1] = Bs[ks * 8 + c + 4][n];
            }
#pragma unroll
            for (int mf = 0; mf < 4; mf++)
#pragma unroll
                for (int nf = 0; nf < 8; nf++)
                    mma_tf32(acc[mf][nf], af[mf], bf[nf]);
        }
        __syncthreads();
    }

    // ---- epilogue ----
    if (EPI == 3) {
        float rsum[4][2];
#pragma unroll
        for (int mf = 0; mf < 4; mf++) { rsum[mf][0] = 0.f; rsum[mf][1] = 0.f; }
#pragma unroll
        for (int mf = 0; mf < 4; mf++)
#pragma unroll
            for (int nf = 0; nf < 8; nf++)
#pragma unroll
                for (int rr = 0; rr < 2; rr++)
#pragma unroll
                    for (int q = 0; q < 2; q++) {
                        int oj = j0 + wn + nf * 8 + 2 * c + q;
                        float v = silu_f(acc[mf][nf][rr * 2 + q] + bias[oj]);
                        rsum[mf][rr] += v * wc2[oj];
                    }
#pragma unroll
        for (int mf = 0; mf < 4; mf++)
#pragma unroll
            for (int rr = 0; rr < 2; rr++) {
                float s = rsum[mf][rr];
                s += __shfl_xor_sync(0xffffffffu, s, 1);
                s += __shfl_xor_sync(0xffffffffu, s, 2);
                if (c == 0) {
                    int oi = i0 + wm + mf * 16 + g + rr * 8;
                    if (oi < M) atomicAdd(&cbuf[oi], s);
                }
            }
        return;
    }

#pragma unroll
    for (int mf = 0; mf < 4; mf++) {
#pragma unroll
        for (int rr = 0; rr < 2; rr++) {
            int oi = i0 + wm + mf * 16 + g + rr * 8;
            if (oi >= M) continue;
            int rE = 0;
            if (EPI == 4) rE = __ldg(&rowIdx[oi]);
#pragma unroll
            for (int nf = 0; nf < 8; nf++) {
#pragma unroll
                for (int q = 0; q < 2; q++) {
                    int oj = j0 + wn + nf * 8 + 2 * c + q;
                    float v = acc[mf][nf][rr * 2 + q] + bias[oj];
                    if (EPI == 1 || EPI == 4) v = silu_f(v);
                    if (EPI == 2) C[(size_t)oi * Ncol + oj] += v;
                    else          C[(size_t)oi * Ncol + oj] = v;
                    if (EPI == 4) atomicAdd(&aggout[(size_t)rE * Hh + oj], v);
                }
            }
        }
    }
}

// ---------------- SIMT SGEMM (small tails only) ----------------------------
template <int EPI>
__global__ void gemm_k(const float* __restrict__ A, const float* __restrict__ Bw,
                       const float* __restrict__ bias, float* __restrict__ C,
                       int M, int K, int Ncol)
{
    __shared__ float As[16][64];
    __shared__ float Bs[16][64];
    const int tid = threadIdx.x;
    const int tx = tid & 15, ty = tid >> 4;
    const int i0 = blockIdx.y * 64, j0 = blockIdx.x * 64;
    const int a_row = tid >> 2, a_k = (tid & 3) * 4;
    const int b_k = tid >> 4, b_j = (tid & 15) * 4;
    float acc[4][4] = {};
    const int gi = i0 + a_row;
    for (int k0 = 0; k0 < K; k0 += 16) {
#pragma unroll
        for (int q = 0; q < 4; q++) {
            int gk = k0 + a_k + q;
            As[a_k + q][a_row] = (gi < M && gk < K) ? A[(size_t)gi * K + gk] : 0.f;
        }
        int gk = k0 + b_k;
#pragma unroll
        for (int q = 0; q < 4; q++) {
            int gj = j0 + b_j + q;
            Bs[b_k][b_j + q] = (gk < K && gj < Ncol) ? Bw[(size_t)gk * Ncol + gj] : 0.f;
        }
        __syncthreads();
#pragma unroll
        for (int kk = 0; kk < 16; kk++) {
            float4 ra = *(const float4*)&As[kk][ty * 4];
            float4 rb = *(const float4*)&Bs[kk][tx * 4];
            float av[4] = {ra.x, ra.y, ra.z, ra.w};
            float bv[4] = {rb.x, rb.y, rb.z, rb.w};
#pragma unroll
            for (int m = 0; m < 4; m++)
#pragma unroll
                for (int n = 0; n < 4; n++) acc[m][n] += av[m] * bv[n];
        }
        __syncthreads();
    }
#pragma unroll
    for (int m = 0; m < 4; m++) {
        int oi = i0 + ty * 4 + m;
        if (oi >= M) continue;
#pragma unroll
        for (int n = 0; n < 4; n++) {
            int oj = j0 + tx * 4 + n;
            if (oj >= Ncol) continue;
            float v = acc[m][n] + bias[oj];
            if (EPI == 1) v = silu_f(v);
            if (EPI == 2) C[(size_t)oi * Ncol + oj] += v;
            else          C[(size_t)oi * Ncol + oj] = v;
        }
    }
}

// ---------------- small helper kernels -------------------------------------
__global__ void init_kernel(const float* __restrict__ pos, float* __restrict__ coord,
                            float* __restrict__ cnt)
{
    int i = blockIdx.x * blockDim.x + threadIdx.x;
    if (i >= Nn) return;
    cnt[i] = 0.f;
    coord[3 * i + 0] = pos[3 * i + 0];
    coord[3 * i + 1] = pos[3 * i + 1];
    coord[3 * i + 2] = pos[3 * i + 2];
}

__global__ void count_kernel(const int* __restrict__ row, float* __restrict__ cnt)
{
    int e = blockIdx.x * blockDim.x + threadIdx.x;
    if (e >= Ee) return;
    atomicAdd(&cnt[row[e]], 1.f);
}

__global__ void edge_geom_kernel(const float* __restrict__ coord,
                                 const int* __restrict__ row, const int* __restrict__ col,
                                 float* __restrict__ diff, float* __restrict__ radial)
{
    int e = blockIdx.x * blockDim.x + threadIdx.x;
    if (e >= Ee) return;
    int r = row[e], c = col[e];
    float dx = coord[3 * r + 0] - coord[3 * c + 0];
    float dy = coord[3 * r + 1] - coord[3 * c + 1];
    float dz = coord[3 * r + 2] - coord[3 * c + 2];
    diff[3 * e + 0] = dx; diff[3 * e + 1] = dy; diff[3 * e + 2] = dz;
    radial[e] = dx * dx + dy * dy + dz * dz;
}

__global__ void zero_kernel(float* __restrict__ p, int n)
{
    int i = blockIdx.x * blockDim.x + threadIdx.x;
    if (i < n) p[i] = 0.f;
}

__global__ void coord_update_kernel(const float* __restrict__ diff, const float* __restrict__ cbuf,
                                    const int* __restrict__ row, const float* __restrict__ cnt,
                                    float* __restrict__ coord)
{
    int e = blockIdx.x * blockDim.x + threadIdx.x;
    if (e >= Ee) return;
    int r = row[e];
    float s = cbuf[e] / fmaxf(cnt[r], 1.f);
    atomicAdd(&coord[3 * r + 0], diff[3 * e + 0] * s);
    atomicAdd(&coord[3 * r + 1], diff[3 * e + 1] * s);
    atomicAdd(&coord[3 * r + 2], diff[3 * e + 2] * s);
}

__global__ void bounds_kernel(const int* __restrict__ batch, int* __restrict__ s,
                              int* __restrict__ e)
{
    int i = blockIdx.x * blockDim.x + threadIdx.x;
    if (i >= Nn) return;
    int b = batch[i];
    if (i == 0) s[b] = 0;
    else {
        int pb = batch[i - 1];
        if (pb != b) { s[b] = i; e[pb] = i; }
    }
    if (i == Nn - 1) e[b] = Nn;
}

__global__ void pool_kernel(const float* __restrict__ hout, const int* __restrict__ s,
                            const int* __restrict__ e, const float* __restrict__ frag,
                            const float* __restrict__ addf, float* __restrict__ z)
{
    int b = blockIdx.x;
    int j = threadIdx.x;  // 256
    float m = -INFINITY;
    int n0 = s[b], n1 = e[b];
    for (int n = n0; n < n1; n++) m = fmaxf(m, hout[(size_t)n * Hh + j]);
    z[b * ZD + j] = m;
    if (j < 8)       z[b * ZD + Hh + j] = frag[b * 8 + j];
    else if (j < 16) z[b * ZD + Hh + j] = addf[b * 8 + (j - 8)];
}

// ---------------- launch ----------------------------------------------------
extern "C" void kernel_launch(void* const* d_in, const int* in_sizes, int n_in,
                              void* d_out, int out_size)
{
    const float* x        = (const float*)d_in[0];
    const float* pos      = (const float*)d_in[1];
    const float* eattr    = (const float*)d_in[2];
    const float* frag     = (const float*)d_in[3];
    const float* addf     = (const float*)d_in[4];
    const int*   eidx     = (const int*)d_in[5];
    const int*   batch    = (const int*)d_in[6];
    const float* emb_in_w = (const float*)d_in[7];
    const float* emb_in_b = (const float*)d_in[8];
    const float* edge_w1  = (const float*)d_in[9];
    const float* edge_b1  = (const float*)d_in[10];
    const float* edge_w2  = (const float*)d_in[11];
    const float* edge_b2  = (const float*)d_in[12];
    const float* node_w1  = (const float*)d_in[13];
    const float* node_b1  = (const float*)d_in[14];
    const float* node_w2  = (const float*)d_in[15];
    const float* node_b2  = (const float*)d_in[16];
    const float* coord_w1 = (const float*)d_in[17];
    const float* coord_b1 = (const float*)d_in[18];
    const float* coord_w2 = (const float*)d_in[19];
    const float* emb_out_w= (const float*)d_in[20];
    const float* emb_out_b= (const float*)d_in[21];
    const float* res_w1   = (const float*)d_in[22];
    const float* res_b1   = (const float*)d_in[23];
    const float* res_w2   = (const float*)d_in[24];
    const float* res_b2   = (const float*)d_in[25];
    const float* head_w   = (const float*)d_in[26];
    const float* head_b   = (const float*)d_in[27];
    float* out = (float*)d_out;
    const int* row = eidx;
    const int* col = eidx + Ee;

    float *h, *hout, *n1, *agg, *coord, *cnt, *diff, *radial, *m1, *m2, *cbuf, *z, *tbuf;
    int *sb, *eb;
    cudaGetSymbolAddress((void**)&h, g_h);
    cudaGetSymbolAddress((void**)&hout, g_hout);
    cudaGetSymbolAddress((void**)&n1, g_n1);
    cudaGetSymbolAddress((void**)&agg, g_agg);
    cudaGetSymbolAddress((void**)&coord, g_coord);
    cudaGetSymbolAddress((void**)&cnt, g_cnt);
    cudaGetSymbolAddress((void**)&diff, g_diff);
    cudaGetSymbolAddress((void**)&radial, g_radial);
    cudaGetSymbolAddress((void**)&m1, g_m1);
    cudaGetSymbolAddress((void**)&m2, g_m2);
    cudaGetSymbolAddress((void**)&cbuf, g_c);
    cudaGetSymbolAddress((void**)&z, g_z);
    cudaGetSymbolAddress((void**)&tbuf, g_t);
    cudaGetSymbolAddress((void**)&sb, g_s);
    cudaGetSymbolAddress((void**)&eb, g_e);

    const dim3 T(256), T128(128);
    const dim3 gE(2, Ee / 128);               // 2 x 2500
    const dim3 gN(2, (Nn + 127) / 128);       // 2 x 157

    init_kernel<<<(Nn + 255) / 256, T>>>(pos, coord, cnt);
    count_kernel<<<(Ee + 255) / 256, T>>>(row, cnt);

    // h = x @ emb_in_w + b
    gemm_tc<0, 0><<<gN, T128>>>(x, emb_in_w, emb_in_b, h, Nn, Ff, Hh,
                                nullptr, nullptr, nullptr, nullptr, nullptr, nullptr,
                                nullptr, nullptr, nullptr);

    for (int l = 0; l < Ll; l++) {
        edge_geom_kernel<<<(Ee + 255) / 256, T>>>(coord, row, col, diff, radial);
        // m1 = silu(concat(h[row],h[col],radial,ea) @ W1 + b1)
        gemm_tc<1, 1><<<gE, T128>>>(nullptr, edge_w1 + (size_t)l * K1 * Hh, edge_b1 + l * Hh,
                                    m1, Ee, K1, Hh, row, col, h, nullptr, radial, eattr,
                                    nullptr, nullptr, nullptr);
        zero_kernel<<<(Nn * Hh + 255) / 256, T>>>(agg, Nn * Hh);
        // m2 = silu(m1 @ W2 + b2); fused: agg[row[e]] += m2[e,:]
        gemm_tc<0, 4><<<gE, T128>>>(m1, edge_w2 + (size_t)l * Hh * Hh, edge_b2 + l * Hh,
                                    m2, Ee, Hh, Hh, row, nullptr, nullptr, nullptr,
                                    nullptr, nullptr, nullptr, nullptr, agg);
        zero_kernel<<<(Ee + 255) / 256, T>>>(cbuf, Ee);
        // c[e] = silu(m2 @ Wc1 + bc1) @ wc2   (fused reduction, no t buffer)
        gemm_tc<0, 3><<<gE, T128>>>(m2, coord_w1 + (size_t)l * Hh * Hh, coord_b1 + l * Hh,
                                    nullptr, Ee, Hh, Hh, nullptr, nullptr, nullptr, nullptr,
                                    nullptr, nullptr, coord_w2 + l * Hh, cbuf, nullptr);
        coord_update_kernel<<<(Ee + 255) / 256, T>>>(diff, cbuf, row, cnt, coord);
        // n1 = silu(concat(h,agg) @ nW1 + nb1)
        gemm_tc<2, 1><<<gN, T128>>>(nullptr, node_w1 + (size_t)l * 2 * Hh * Hh, node_b1 + l * Hh,
                                    n1, Nn, 2 * Hh, Hh, nullptr, nullptr, h, agg,
                                    nullptr, nullptr, nullptr, nullptr, nullptr);
        // h += n1 @ nW2 + nb2
        gemm_tc<0, 2><<<gN, T128>>>(n1, node_w2 + (size_t)l * Hh * Hh, node_b2 + l * Hh,
                                    h, Nn, Hh, Hh, nullptr, nullptr, nullptr, nullptr,
                                    nullptr, nullptr, nullptr, nullptr, nullptr);
    }

    // hout = h @ emb_out_w + b
    gemm_tc<0, 0><<<gN, T128>>>(h, emb_out_w, emb_out_b, hout, Nn, Hh, Hh,
                                nullptr, nullptr, nullptr, nullptr, nullptr, nullptr,
                                nullptr, nullptr, nullptr);

    bounds_kernel<<<(Nn + 255) / 256, T>>>(batch, sb, eb);
    pool_kernel<<<Bb, T>>>(hout, sb, eb, frag, addf, z);

    // t = silu(z @ res_w1 + b)
    gemm_k<1><<<dim3(4, 2), T>>>(z, res_w1, res_b1, tbuf, Bb, ZD, Hh);
    // z += t @ res_w2 + b
    gemm_k<2><<<dim3((ZD + 63) / 64, 2), T>>>(tbuf, res_w2, res_b2, z, Bb, Hh, ZD);
    // out = z @ head_w + head_b
    gemm_k<0><<<dim3((Pp + 63) / 64, 2), T>>>(z, head_w, head_b, out, Bb, ZD, Pp);
}

// round 4
// speedup vs baseline: 4.2272x; 1.4045x over previous
#include <cuda_runtime.h>
#include <math.h>
#include <stdint.h>

// Problem constants (fixed by the dataset)
#define Nn 20000
#define Ee 320000
#define Bb 128
#define Ff 128
#define Hh 256
#define EDd 16
#define Gg 16
#define Pp 2000
#define Ll 4
#define ZD (Hh + Gg)          // 272
#define K1 (2 * Hh + 1 + EDd) // 529

// ---------------- scratch (device globals; no allocation allowed) ----------
__device__ float g_h[Nn * Hh];
__device__ float g_hout[Nn * Hh];
__device__ float g_n1[Nn * Hh];
__device__ float g_agg[Nn * Hh];
__device__ float g_coord[Nn * 3];
__device__ float g_cnt[Nn];
__device__ float g_diff[Ee * 3];
__device__ float g_radial[Ee];
__device__ float g_m1[(size_t)Ee * Hh];
__device__ float g_m2[(size_t)Ee * Hh];
__device__ float g_c[Ee];
__device__ float g_z[Bb * ZD];
__device__ float g_t[Bb * Hh];
__device__ int   g_s[Bb];
__device__ int   g_e[Bb];

__device__ __forceinline__ void mma_tf32(float* d, const uint32_t* a, const uint32_t* b) {
    asm volatile(
        "mma.sync.aligned.m16n8k8.row.col.f32.tf32.tf32.f32 "
        "{%0,%1,%2,%3}, {%4,%5,%6,%7}, {%8,%9}, {%0,%1,%2,%3};"
        : "+f"(d[0]), "+f"(d[1]), "+f"(d[2]), "+f"(d[3])
        : "r"(a[0]), "r"(a[1]), "r"(a[2]), "r"(a[3]), "r"(b[0]), "r"(b[1]));
}

__device__ __forceinline__ void cpa16(uint32_t saddr, const void* gptr) {
    asm volatile("cp.async.cg.shared.global [%0], [%1], 16;" :: "r"(saddr), "l"(gptr));
}

__device__ __forceinline__ float silu_f(float v) { return v / (1.f + expf(-v)); }

// ---------------- tf32 tensor-core GEMM (cp.async double-buffered) ---------
// C[M,Ncol] = epi( A'[M,K] @ Bw[K,Ncol] + bias ), Ncol == 256 tile space,
// block tile 128x128, 256 threads, warp tile 32x64, K-chunk 16, 2 stages.
// AMODE 0: A plain row-major (K % 4 == 0 required for cp.async path)
// AMODE 1: A(i,k) = k<H ? h[row[i],k] : k<2H ? h[col[i],k-H] : k==2H ? radial[i]
//                   : edge_attr[i,k-2H-1]   (K=529)
// AMODE 2: A(i,k) = k<H ? h[i,k] : agg[i,k-H]   (K=512)
// EPI 0: C=v ; 1: C=silu(v) ; 2: C+=v
// EPI 3: no C write; cbuf[i] += sum_j silu(v_ij)*wc2[j]   (atomic)
// EPI 4: C=silu(v) AND agg[row[i]] += silu(v)             (atomic)
template <int AMODE, int EPI>
__global__ __launch_bounds__(256, 2)
void gemm_tc(const float* __restrict__ A, const float* __restrict__ Bw,
             const float* __restrict__ bias, float* __restrict__ C,
             int M, int K, int Ncol,
             const int* __restrict__ rowIdx, const int* __restrict__ colIdx,
             const float* __restrict__ hbuf, const float* __restrict__ aggbuf,
             const float* __restrict__ radial, const float* __restrict__ eattr,
             const float* __restrict__ wc2, float* __restrict__ cbuf,
             float* __restrict__ aggout)
{
    __shared__ float As[2][128][20];   // [stage][m][k] pad 20 -> conflict-free
    __shared__ float Bs[2][16][136];   // [stage][k][n] pad 136 -> conflict-free

    const int tid  = threadIdx.x;
    const int lane = tid & 31;
    const int wid  = tid >> 5;            // 0..7
    const int wm   = (wid >> 1) * 32;     // 4 warps along M
    const int wn   = (wid & 1) * 64;      // 2 warps along N
    const int g    = lane >> 2;
    const int c    = lane & 3;

    const int i0 = blockIdx.y * 128;
    const int j0 = blockIdx.x * 128;

    // A loader: thread pair per row
    const int arow  = tid >> 1;           // 0..127
    const int acol8 = (tid & 1) * 8;      // 0 or 8
    const int gi_a  = i0 + arow;
    const bool aok  = gi_a < M;
    int rA = 0, cA = 0;
    if (AMODE == 1 && aok) { rA = __ldg(&rowIdx[gi_a]); cA = __ldg(&colIdx[gi_a]); }

    const int nch = (K + 15) / 16;

    auto load_stage = [&](int st, int k0) {
        // ---- A chunk: rows 0..127, k0..k0+15 ----
        if (AMODE == 1 && k0 >= 512) {
#pragma unroll
            for (int jj = 0; jj < 8; jj++) {
                int gk = k0 + acol8 + jj;
                float v = 0.f;
                if (aok && gk < K) {
                    v = (gk == 2 * Hh) ? radial[gi_a]
                                       : eattr[gi_a * EDd + gk - (2 * Hh + 1)];
                }
                As[st][arow][acol8 + jj] = v;
            }
        } else if (!aok) {
#pragma unroll
            for (int jj = 0; jj < 8; jj++) As[st][arow][acol8 + jj] = 0.f;
        } else {
            const float* base;
            if (AMODE == 0)      base = A + (size_t)gi_a * K + k0;
            else if (AMODE == 1) base = (k0 < Hh) ? hbuf + (size_t)rA * Hh + k0
                                                  : hbuf + (size_t)cA * Hh + (k0 - Hh);
            else                 base = (k0 < Hh) ? hbuf + (size_t)gi_a * Hh + k0
                                                  : aggbuf + (size_t)gi_a * Hh + (k0 - Hh);
            uint32_t s = (uint32_t)__cvta_generic_to_shared(&As[st][arow][acol8]);
            cpa16(s, base + acol8);
            cpa16(s + 16, base + acol8 + 4);
        }
        // ---- B chunk: 16 rows x 128 cols ----
#pragma unroll
        for (int it = 0; it < 2; it++) {
            int lin  = it * 256 + tid;          // 0..511 float4 slots
            int brow = lin >> 5;                // 0..15
            int bcol = (lin & 31) * 4;          // 0..124
            int gk = k0 + brow;
            uint32_t s = (uint32_t)__cvta_generic_to_shared(&Bs[st][brow][bcol]);
            if (gk < K) cpa16(s, &Bw[(size_t)gk * Ncol + j0 + bcol]);
            else {
                Bs[st][brow][bcol + 0] = 0.f; Bs[st][brow][bcol + 1] = 0.f;
                Bs[st][brow][bcol + 2] = 0.f; Bs[st][brow][bcol + 3] = 0.f;
            }
        }
    };

    float acc[2][8][4];
#pragma unroll
    for (int a = 0; a < 2; a++)
#pragma unroll
        for (int b = 0; b < 8; b++)
#pragma unroll
            for (int q = 0; q < 4; q++) acc[a][b][q] = 0.f;

    load_stage(0, 0);
    asm volatile("cp.async.commit_group;");

    for (int ch = 0; ch < nch; ch++) {
        int st = ch & 1;
        if (ch + 1 < nch) {
            load_stage(st ^ 1, (ch + 1) * 16);
            asm volatile("cp.async.commit_group;");
            asm volatile("cp.async.wait_group 1;");
        } else {
            asm volatile("cp.async.wait_group 0;");
        }
        __syncthreads();

#pragma unroll
        for (int ks = 0; ks < 2; ks++) {
            uint32_t af[2][4];
#pragma unroll
            for (int mf = 0; mf < 2; mf++) {
                int m = wm + mf * 16 + g;
                af[mf][0] = __float_as_uint(As[st][m][ks * 8 + c]);
                af[mf][1] = __float_as_uint(As[st][m + 8][ks * 8 + c]);
                af[mf][2] = __float_as_uint(As[st][m][ks * 8 + c + 4]);
                af[mf][3] = __float_as_uint(As[st][m + 8][ks * 8 + c + 4]);
            }
            uint32_t bf[8][2];
#pragma unroll
            for (int nf = 0; nf < 8; nf++) {
                int n = wn + nf * 8 + g;
                bf[nf][0] = __float_as_uint(Bs[st][ks * 8 + c][n]);
                bf[nf][1] = __float_as_uint(Bs[st][ks * 8 + c + 4][n]);
            }
#pragma unroll
            for (int mf = 0; mf < 2; mf++)
#pragma unroll
                for (int nf = 0; nf < 8; nf++)
                    mma_tf32(acc[mf][nf], af[mf], bf[nf]);
        }
        __syncthreads();
    }

    // ---- epilogue ----
    if (EPI == 3) {
        float rsum[2][2];
#pragma unroll
        for (int mf = 0; mf < 2; mf++) { rsum[mf][0] = 0.f; rsum[mf][1] = 0.f; }
#pragma unroll
        for (int mf = 0; mf < 2; mf++)
#pragma unroll
            for (int nf = 0; nf < 8; nf++)
#pragma unroll
                for (int rr = 0; rr < 2; rr++)
#pragma unroll
                    for (int q = 0; q < 2; q++) {
                        int oj = j0 + wn + nf * 8 + 2 * c + q;
                        float v = silu_f(acc[mf][nf][rr * 2 + q] + bias[oj]);
                        rsum[mf][rr] += v * wc2[oj];
                    }
#pragma unroll
        for (int mf = 0; mf < 2; mf++)
#pragma unroll
            for (int rr = 0; rr < 2; rr++) {
                float s = rsum[mf][rr];
                s += __shfl_xor_sync(0xffffffffu, s, 1);
                s += __shfl_xor_sync(0xffffffffu, s, 2);
                if (c == 0) {
                    int oi = i0 + wm + mf * 16 + g + rr * 8;
                    if (oi < M) atomicAdd(&cbuf[oi], s);
                }
            }
        return;
    }

#pragma unroll
    for (int mf = 0; mf < 2; mf++) {
#pragma unroll
        for (int rr = 0; rr < 2; rr++) {
            int oi = i0 + wm + mf * 16 + g + rr * 8;
            if (oi >= M) continue;
            int rE = 0;
            if (EPI == 4) rE = __ldg(&rowIdx[oi]);
#pragma unroll
            for (int nf = 0; nf < 8; nf++) {
#pragma unroll
                for (int q = 0; q < 2; q++) {
                    int oj = j0 + wn + nf * 8 + 2 * c + q;
                    float v = acc[mf][nf][rr * 2 + q] + bias[oj];
                    if (EPI == 1 || EPI == 4) v = silu_f(v);
                    if (EPI == 2) C[(size_t)oi * Ncol + oj] += v;
                    else          C[(size_t)oi * Ncol + oj] = v;
                    if (EPI == 4) atomicAdd(&aggout[(size_t)rE * Hh + oj], v);
                }
            }
        }
    }
}

// ---------------- SIMT SGEMM (small tails only) ----------------------------
template <int EPI>
__global__ void gemm_k(const float* __restrict__ A, const float* __restrict__ Bw,
                       const float* __restrict__ bias, float* __restrict__ C,
                       int M, int K, int Ncol)
{
    __shared__ float As[16][64];
    __shared__ float Bs[16][64];
    const int tid = threadIdx.x;
    const int tx = tid & 15, ty = tid >> 4;
    const int i0 = blockIdx.y * 64, j0 = blockIdx.x * 64;
    const int a_row = tid >> 2, a_k = (tid & 3) * 4;
    const int b_k = tid >> 4, b_j = (tid & 15) * 4;
    float acc[4][4] = {};
    const int gi = i0 + a_row;
    for (int k0 = 0; k0 < K; k0 += 16) {
#pragma unroll
        for (int q = 0; q < 4; q++) {
            int gk = k0 + a_k + q;
            As[a_k + q][a_row] = (gi < M && gk < K) ? A[(size_t)gi * K + gk] : 0.f;
        }
        int gk = k0 + b_k;
#pragma unroll
        for (int q = 0; q < 4; q++) {
            int gj = j0 + b_j + q;
            Bs[b_k][b_j + q] = (gk < K && gj < Ncol) ? Bw[(size_t)gk * Ncol + gj] : 0.f;
        }
        __syncthreads();
#pragma unroll
        for (int kk = 0; kk < 16; kk++) {
            float4 ra = *(const float4*)&As[kk][ty * 4];
            float4 rb = *(const float4*)&Bs[kk][tx * 4];
            float av[4] = {ra.x, ra.y, ra.z, ra.w};
            float bv[4] = {rb.x, rb.y, rb.z, rb.w};
#pragma unroll
            for (int m = 0; m < 4; m++)
#pragma unroll
                for (int n = 0; n < 4; n++) acc[m][n] += av[m] * bv[n];
        }
        __syncthreads();
    }
#pragma unroll
    for (int m = 0; m < 4; m++) {
        int oi = i0 + ty * 4 + m;
        if (oi >= M) continue;
#pragma unroll
        for (int n = 0; n < 4; n++) {
            int oj = j0 + tx * 4 + n;
            if (oj >= Ncol) continue;
            float v = acc[m][n] + bias[oj];
            if (EPI == 1) v = silu_f(v);
            if (EPI == 2) C[(size_t)oi * Ncol + oj] += v;
            else          C[(size_t)oi * Ncol + oj] = v;
        }
    }
}

// ---------------- small helper kernels -------------------------------------
__global__ void init_kernel(const float* __restrict__ pos, float* __restrict__ coord,
                            float* __restrict__ cnt)
{
    int i = blockIdx.x * blockDim.x + threadIdx.x;
    if (i >= Nn) return;
    cnt[i] = 0.f;
    coord[3 * i + 0] = pos[3 * i + 0];
    coord[3 * i + 1] = pos[3 * i + 1];
    coord[3 * i + 2] = pos[3 * i + 2];
}

__global__ void count_kernel(const int* __restrict__ row, float* __restrict__ cnt)
{
    int e = blockIdx.x * blockDim.x + threadIdx.x;
    if (e >= Ee) return;
    atomicAdd(&cnt[row[e]], 1.f);
}

__global__ void edge_geom_kernel(const float* __restrict__ coord,
                                 const int* __restrict__ row, const int* __restrict__ col,
                                 float* __restrict__ diff, float* __restrict__ radial)
{
    int e = blockIdx.x * blockDim.x + threadIdx.x;
    if (e >= Ee) return;
    int r = row[e], c = col[e];
    float dx = coord[3 * r + 0] - coord[3 * c + 0];
    float dy = coord[3 * r + 1] - coord[3 * c + 1];
    float dz = coord[3 * r + 2] - coord[3 * c + 2];
    diff[3 * e + 0] = dx; diff[3 * e + 1] = dy; diff[3 * e + 2] = dz;
    radial[e] = dx * dx + dy * dy + dz * dz;
}

__global__ void zero_kernel(float* __restrict__ p, int n)
{
    int i = blockIdx.x * blockDim.x + threadIdx.x;
    if (i < n) p[i] = 0.f;
}

__global__ void coord_update_kernel(const float* __restrict__ diff, const float* __restrict__ cbuf,
                                    const int* __restrict__ row, const float* __restrict__ cnt,
                                    float* __restrict__ coord)
{
    int e = blockIdx.x * blockDim.x + threadIdx.x;
    if (e >= Ee) return;
    int r = row[e];
    float s = cbuf[e] / fmaxf(cnt[r], 1.f);
    atomicAdd(&coord[3 * r + 0], diff[3 * e + 0] * s);
    atomicAdd(&coord[3 * r + 1], diff[3 * e + 1] * s);
    atomicAdd(&coord[3 * r + 2], diff[3 * e + 2] * s);
}

__global__ void bounds_kernel(const int* __restrict__ batch, int* __restrict__ s,
                              int* __restrict__ e)
{
    int i = blockIdx.x * blockDim.x + threadIdx.x;
    if (i >= Nn) return;
    int b = batch[i];
    if (i == 0) s[b] = 0;
    else {
        int pb = batch[i - 1];
        if (pb != b) { s[b] = i; e[pb] = i; }
    }
    if (i == Nn - 1) e[b] = Nn;
}

__global__ void pool_kernel(const float* __restrict__ hout, const int* __restrict__ s,
                            const int* __restrict__ e, const float* __restrict__ frag,
                            const float* __restrict__ addf, float* __restrict__ z)
{
    int b = blockIdx.x;
    int j = threadIdx.x;  // 256
    float m = -INFINITY;
    int n0 = s[b], n1 = e[b];
    for (int n = n0; n < n1; n++) m = fmaxf(m, hout[(size_t)n * Hh + j]);
    z[b * ZD + j] = m;
    if (j < 8)       z[b * ZD + Hh + j] = frag[b * 8 + j];
    else if (j < 16) z[b * ZD + Hh + j] = addf[b * 8 + (j - 8)];
}

// ---------------- launch ----------------------------------------------------
extern "C" void kernel_launch(void* const* d_in, const int* in_sizes, int n_in,
                              void* d_out, int out_size)
{
    const float* x        = (const float*)d_in[0];
    const float* pos      = (const float*)d_in[1];
    const float* eattr    = (const float*)d_in[2];
    const float* frag     = (const float*)d_in[3];
    const float* addf     = (const float*)d_in[4];
    const int*   eidx     = (const int*)d_in[5];
    const int*   batch    = (const int*)d_in[6];
    const float* emb_in_w = (const float*)d_in[7];
    const float* emb_in_b = (const float*)d_in[8];
    const float* edge_w1  = (const float*)d_in[9];
    const float* edge_b1  = (const float*)d_in[10];
    const float* edge_w2  = (const float*)d_in[11];
    const float* edge_b2  = (const float*)d_in[12];
    const float* node_w1  = (const float*)d_in[13];
    const float* node_b1  = (const float*)d_in[14];
    const float* node_w2  = (const float*)d_in[15];
    const float* node_b2  = (const float*)d_in[16];
    const float* coord_w1 = (const float*)d_in[17];
    const float* coord_b1 = (const float*)d_in[18];
    const float* coord_w2 = (const float*)d_in[19];
    const float* emb_out_w= (const float*)d_in[20];
    const float* emb_out_b= (const float*)d_in[21];
    const float* res_w1   = (const float*)d_in[22];
    const float* res_b1   = (const float*)d_in[23];
    const float* res_w2   = (const float*)d_in[24];
    const float* res_b2   = (const float*)d_in[25];
    const float* head_w   = (const float*)d_in[26];
    const float* head_b   = (const float*)d_in[27];
    float* out = (float*)d_out;
    const int* row = eidx;
    const int* col = eidx + Ee;

    float *h, *hout, *n1, *agg, *coord, *cnt, *diff, *radial, *m1, *m2, *cbuf, *z, *tbuf;
    int *sb, *eb;
    cudaGetSymbolAddress((void**)&h, g_h);
    cudaGetSymbolAddress((void**)&hout, g_hout);
    cudaGetSymbolAddress((void**)&n1, g_n1);
    cudaGetSymbolAddress((void**)&agg, g_agg);
    cudaGetSymbolAddress((void**)&coord, g_coord);
    cudaGetSymbolAddress((void**)&cnt, g_cnt);
    cudaGetSymbolAddress((void**)&diff, g_diff);
    cudaGetSymbolAddress((void**)&radial, g_radial);
    cudaGetSymbolAddress((void**)&m1, g_m1);
    cudaGetSymbolAddress((void**)&m2, g_m2);
    cudaGetSymbolAddress((void**)&cbuf, g_c);
    cudaGetSymbolAddress((void**)&z, g_z);
    cudaGetSymbolAddress((void**)&tbuf, g_t);
    cudaGetSymbolAddress((void**)&sb, g_s);
    cudaGetSymbolAddress((void**)&eb, g_e);

    const dim3 T(256), T256(256);
    const dim3 gE(2, Ee / 128);               // 2 x 2500
    const dim3 gN(2, (Nn + 127) / 128);       // 2 x 157

    init_kernel<<<(Nn + 255) / 256, T>>>(pos, coord, cnt);
    count_kernel<<<(Ee + 255) / 256, T>>>(row, cnt);

    // h = x @ emb_in_w + b
    gemm_tc<0, 0><<<gN, T256>>>(x, emb_in_w, emb_in_b, h, Nn, Ff, Hh,
                                nullptr, nullptr, nullptr, nullptr, nullptr, nullptr,
                                nullptr, nullptr, nullptr);

    for (int l = 0; l < Ll; l++) {
        edge_geom_kernel<<<(Ee + 255) / 256, T>>>(coord, row, col, diff, radial);
        // m1 = silu(concat(h[row],h[col],radial,ea) @ W1 + b1)
        gemm_tc<1, 1><<<gE, T256>>>(nullptr, edge_w1 + (size_t)l * K1 * Hh, edge_b1 + l * Hh,
                                    m1, Ee, K1, Hh, row, col, h, nullptr, radial, eattr,
                                    nullptr, nullptr, nullptr);
        zero_kernel<<<(Nn * Hh + 255) / 256, T>>>(agg, Nn * Hh);
        // m2 = silu(m1 @ W2 + b2); fused: agg[row[e]] += m2[e,:]
        gemm_tc<0, 4><<<gE, T256>>>(m1, edge_w2 + (size_t)l * Hh * Hh, edge_b2 + l * Hh,
                                    m2, Ee, Hh, Hh, row, nullptr, nullptr, nullptr,
                                    nullptr, nullptr, nullptr, nullptr, agg);
        zero_kernel<<<(Ee + 255) / 256, T>>>(cbuf, Ee);
        // c[e] = silu(m2 @ Wc1 + bc1) @ wc2   (fused reduction, no t buffer)
        gemm_tc<0, 3><<<gE, T256>>>(m2, coord_w1 + (size_t)l * Hh * Hh, coord_b1 + l * Hh,
                                    nullptr, Ee, Hh, Hh, nullptr, nullptr, nullptr, nullptr,
                                    nullptr, nullptr, coord_w2 + l * Hh, cbuf, nullptr);
        coord_update_kernel<<<(Ee + 255) / 256, T>>>(diff, cbuf, row, cnt, coord);
        // n1 = silu(concat(h,agg) @ nW1 + nb1)
        gemm_tc<2, 1><<<gN, T256>>>(nullptr, node_w1 + (size_t)l * 2 * Hh * Hh, node_b1 + l * Hh,
                                    n1, Nn, 2 * Hh, Hh, nullptr, nullptr, h, agg,
                                    nullptr, nullptr, nullptr, nullptr, nullptr);
        // h += n1 @ nW2 + nb2
        gemm_tc<0, 2><<<gN, T256>>>(n1, node_w2 + (size_t)l * Hh * Hh, node_b2 + l * Hh,
                                    h, Nn, Hh, Hh, nullptr, nullptr, nullptr, nullptr,
                                    nullptr, nullptr, nullptr, nullptr, nullptr);
    }

    // hout = h @ emb_out_w + b
    gemm_tc<0, 0><<<gN, T256>>>(h, emb_out_w, emb_out_b, hout, Nn, Hh, Hh,
                                nullptr, nullptr, nullptr, nullptr, nullptr, nullptr,
                                nullptr, nullptr, nullptr);

    bounds_kernel<<<(Nn + 255) / 256, T>>>(batch, sb, eb);
    pool_kernel<<<Bb, T>>>(hout, sb, eb, frag, addf, z);

    // t = silu(z @ res_w1 + b)
    gemm_k<1><<<dim3(4, 2), T>>>(z, res_w1, res_b1, tbuf, Bb, ZD, Hh);
    // z += t @ res_w2 + b
    gemm_k<2><<<dim3((ZD + 63) / 64, 2), T>>>(tbuf, res_w2, res_b2, z, Bb, Hh, ZD);
    // out = z @ head_w + head_b
    gemm_k<0><<<dim3((Pp + 63) / 64, 2), T>>>(z, head_w, head_b, out, Bb, ZD, Pp);
}